// round 6
// baseline (speedup 1.0000x reference)
#include <cuda_runtime.h>
#include <cstdint>

// ---------------------------------------------------------------------------
// UnionLayer: prefix-mask token compaction + broadcast add of node embedding.
//
// Outputs (concatenated float32 in d_out):
//   [0)              new_x    : (B, N*T, D)
//   [NX)             new_mask : (B, N*T)
//   [NX+BNT)         doclen   : (B,)
//   [NX+BNT+B)       new_tag  : (B, N*T)
//
// Prefix mask => compaction dest == seg_off[b,n] + t, so the inverse map is
// a binary search over the per-batch segment-offset table. Two kernels only.
// ---------------------------------------------------------------------------

#define MAX_B   64
#define MAX_BN  8192

__device__ int g_seg_off[MAX_BN + MAX_B];  // B * (N+1) exclusive offsets
__device__ int g_doclen[MAX_B];

// Kernel 1: per-batch inclusive scan of length -> exclusive seg offsets + doclen
__global__ void k_scan(const int* __restrict__ length, float* __restrict__ out_doclen, int N)
{
    int b = blockIdx.x;
    extern __shared__ int s[];
    int n = threadIdx.x;            // blockDim.x == N
    int v = length[b * N + n];
    s[n] = v;
    __syncthreads();
    for (int off = 1; off < N; off <<= 1) {
        int t = (n >= off) ? s[n - off] : 0;
        __syncthreads();
        s[n] += t;
        __syncthreads();
    }
    g_seg_off[b * (N + 1) + n + 1] = s[n];
    if (n == 0) g_seg_off[b * (N + 1)] = 0;
    if (n == N - 1) {
        g_doclen[b] = s[n];
        if (out_doclen) out_doclen[b] = (float)s[n];
    }
}

// Kernel 2: one warp per output row. Warp-uniform binary search recovers the
// source token; lanes stream 64B each (4x float4, MLP=8). Lane 0 also emits
// the compacted tag and the mask value for this row.
__global__ void __launch_bounds__(256)
k_main(const float4* __restrict__ x4,
       const float4* __restrict__ gcn4,
       float4* __restrict__ out4,
       const int* __restrict__ tags32, int tag_stride,
       float* __restrict__ mask_out, float* __restrict__ tag_out,
       int N, int T, int NT, int Dv, int BNT)
{
    int warp = (blockIdx.x * blockDim.x + threadIdx.x) >> 5;
    int lane = threadIdx.x & 31;
    int row  = warp;                     // row in [0, B*NT)
    if (row >= BNT) return;

    int b = row / NT;
    int j = row - b * NT;
    bool valid = j < g_doclen[b];

    const float4* __restrict__ g = gcn4 + (size_t)(b * N + j / T) * Dv;
    float4* __restrict__ o = out4 + (size_t)row * Dv;

    if (valid) {
        // binary search: largest n with seg_off[n] <= j  (warp-uniform)
        const int* __restrict__ p = g_seg_off + b * (N + 1);
        int lo = 0, hi = N;
        while (hi - lo > 1) {
            int mid = (lo + hi) >> 1;
            if (p[mid] <= j) lo = mid; else hi = mid;
        }
        int t = j - p[lo];
        int srcflat = lo * T + t;                    // within batch
        if (lane == 0) {
            if (mask_out) mask_out[row] = 1.0f;
            if (tag_out)
                tag_out[row] = (float)tags32[(size_t)(b * NT + srcflat) * tag_stride];
        }
        const float4* __restrict__ xr = x4 + ((size_t)b * NT + srcflat) * Dv;
        for (int d0 = lane * 4; d0 < Dv; d0 += 128) {
            float4 g0 = g[d0 + 0], g1 = g[d0 + 1], g2 = g[d0 + 2], g3 = g[d0 + 3];
            float4 x0 = __ldcs(&xr[d0 + 0]);
            float4 x1 = __ldcs(&xr[d0 + 1]);
            float4 x2 = __ldcs(&xr[d0 + 2]);
            float4 x3 = __ldcs(&xr[d0 + 3]);
            g0.x += x0.x; g0.y += x0.y; g0.z += x0.z; g0.w += x0.w;
            g1.x += x1.x; g1.y += x1.y; g1.z += x1.z; g1.w += x1.w;
            g2.x += x2.x; g2.y += x2.y; g2.z += x2.z; g2.w += x2.w;
            g3.x += x3.x; g3.y += x3.y; g3.z += x3.z; g3.w += x3.w;
            __stcs(&o[d0 + 0], g0);
            __stcs(&o[d0 + 1], g1);
            __stcs(&o[d0 + 2], g2);
            __stcs(&o[d0 + 3], g3);
        }
    } else {
        if (lane == 0) {
            if (mask_out) mask_out[row] = 0.0f;
            if (tag_out)  tag_out[row]  = 0.0f;
        }
        for (int d0 = lane * 4; d0 < Dv; d0 += 128) {
            __stcs(&o[d0 + 0], g[d0 + 0]);
            __stcs(&o[d0 + 1], g[d0 + 1]);
            __stcs(&o[d0 + 2], g[d0 + 2]);
            __stcs(&o[d0 + 3], g[d0 + 3]);
        }
    }
}

extern "C" void kernel_launch(void* const* d_in, const int* in_sizes, int n_in,
                              void* d_out, int out_size)
{
    const float* x      = (const float*)d_in[0];   // (B,N,T,D)
    const float* x_gcn  = (const float*)d_in[1];   // (B,N,D)
    // d_in[2] = mask (unused: prefix mask is equivalent to length)
    const int*   length = (const int*)d_in[3];     // (B,N)
    const int*   tags32 = (const int*)d_in[4];     // (B,N,T) int32 (or int64 lo-words)

    const int NX  = in_sizes[0];          // B*N*T*D
    const int BN  = in_sizes[3];          // B*N
    const int BNT = in_sizes[2];          // B*N*T
    const int T   = BNT / BN;
    const int D   = in_sizes[1] / BN;

    // tags may be int32 (stride 1) or int64 viewed as int32 pairs (stride 2)
    const int tag_stride = (in_sizes[4] == 2 * BNT) ? 2 : 1;

    // Derive B from the full-concat output layout; fall back to new_x-only.
    int B = out_size - NX - 2 * BNT;
    bool full = (B >= 1 && B <= MAX_B && (BN % B) == 0);
    if (!full) {
        B = 8;
        if (BN % B) B = 1;
    }
    const int N  = BN / B;
    const int NT = N * T;

    float* out       = (float*)d_out;
    float* mask_out  = full ? out + NX             : nullptr;
    float* dlen_out  = full ? out + NX + BNT       : nullptr;
    float* tag_out   = full ? out + NX + BNT + B   : nullptr;

    // 1) segment offset scan (B blocks, N threads)
    k_scan<<<B, N, N * (int)sizeof(int)>>>(length, dlen_out, N);

    // 2) gather + add + tag + mask (one warp per output row)
    {
        const int Dv = D / 4;
        const int warps_per_block = 256 / 32;
        int blocks = (BNT + warps_per_block - 1) / warps_per_block;
        k_main<<<blocks, 256>>>((const float4*)x, (const float4*)x_gcn, (float4*)out,
                                tags32, tag_stride, mask_out, tag_out,
                                N, T, NT, Dv, BNT);
    }
}